// round 2
// baseline (speedup 1.0000x reference)
#include <cuda_runtime.h>
#include <cuda_bf16.h>
#include <cstdint>

// ---------------------------------------------------------------------------
// GraphSAGE layer:
//   agg[d] += x[s] over bidirectional edges; deg[d] += 1
//   out = relu( x @ Ws^T + (agg/max(deg,1)) @ Wn^T + bias )
// N = 100000, in_dim = out_dim = 128, E = 800000 (undirected input, both dirs)
// edge_index dtype is detected at runtime (JAX may emit int32 or int64).
// ---------------------------------------------------------------------------

#define MAXN 100000
#define DIM  128

// Scratch (allocation-free rule: __device__ globals)
__device__ __align__(16) float g_agg[(size_t)MAXN * DIM];
__device__ __align__(16) float g_deg[MAXN];
__device__ int g_is64;   // 1 if edge_index is int64, 0 if int32

// ---------------------------------------------------------------------------
// Kernel 1: zero agg + deg, and probe edge_index dtype.
// int32 data read as int64 gives idx_even + idx_odd * 2^32; all-4 < N only if
// four odd indices are all zero (p ~ 1e-20). Genuine int64 indices are < N.
// ---------------------------------------------------------------------------
__global__ void zero_probe_kernel(const long long* __restrict__ ei64,
                                  int n_agg4, int n_deg, long long N) {
    int i = blockIdx.x * blockDim.x + threadIdx.x;
    int stride = gridDim.x * blockDim.x;
    if (i == 0) {
        int is64 = 1;
#pragma unroll
        for (int k = 0; k < 4; k++) {
            unsigned long long v = (unsigned long long)ei64[k];
            if (v >= (unsigned long long)N) is64 = 0;
        }
        g_is64 = is64;
    }
    float4 z = make_float4(0.f, 0.f, 0.f, 0.f);
    float4* agg4 = reinterpret_cast<float4*>(g_agg);
    for (int k = i; k < n_agg4; k += stride) agg4[k] = z;
    for (int k = i; k < n_deg; k += stride) g_deg[k] = 0.f;
}

// ---------------------------------------------------------------------------
// Kernel 2: edge scatter. One warp per UNDIRECTED edge; does both directions.
// Vector red.global.add.v4.f32 -> 1 atomic op per lane per direction.
// ---------------------------------------------------------------------------
__device__ __forceinline__ void red_add_v4(float* dst, float4 v) {
    asm volatile("red.global.add.v4.f32 [%0], {%1, %2, %3, %4};"
                 :: "l"(dst), "f"(v.x), "f"(v.y), "f"(v.z), "f"(v.w)
                 : "memory");
}

__global__ void scatter_kernel(const float* __restrict__ x,
                               const void* __restrict__ ei_raw,
                               int E, int N) {
    int gw = (blockIdx.x * blockDim.x + threadIdx.x) >> 5;   // warp id = edge id
    int lane = threadIdx.x & 31;
    if (gw >= E) return;

    long long s, d;
    if (g_is64) {
        const long long* ei = (const long long*)ei_raw;
        s = ei[gw];
        d = ei[(size_t)E + gw];
    } else {
        const int* ei = (const int*)ei_raw;
        s = ei[gw];
        d = ei[(size_t)E + gw];
    }
    // defensive bounds guard: wrong answer beats illegal access
    if ((unsigned long long)s >= (unsigned long long)N ||
        (unsigned long long)d >= (unsigned long long)N) return;

    // forward: x[s] -> agg[d]
    float4 vs = *reinterpret_cast<const float4*>(x + (size_t)s * DIM + lane * 4);
    red_add_v4(g_agg + (size_t)d * DIM + lane * 4, vs);
    // reverse: x[d] -> agg[s]
    float4 vd = *reinterpret_cast<const float4*>(x + (size_t)d * DIM + lane * 4);
    red_add_v4(g_agg + (size_t)s * DIM + lane * 4, vd);

    if (lane == 0) {
        atomicAdd(&g_deg[d], 1.0f);
        atomicAdd(&g_deg[s], 1.0f);
    }
}

// ---------------------------------------------------------------------------
// Kernel 3: fused SGEMM  out = relu([x | agg*scale] @ [Ws|Wn]^T + bias)
// M = N nodes, K = 256 (virtual concat), Ncols = 128.
// Tile: BM=128 x BN=128, BK=32, 256 threads, 8x8 register micro-tile.
// ---------------------------------------------------------------------------
#define BM 128
#define BN 128
#define BK 32

__global__ __launch_bounds__(256) void gemm_kernel(
    const float* __restrict__ x,
    const float* __restrict__ Ws,
    const float* __restrict__ Wn,
    const float* __restrict__ bias,
    float* __restrict__ out,
    int N)
{
    __shared__ float As[BK][BM];
    __shared__ float Bs[BK][BN];

    int tid = threadIdx.x;
    int r0  = blockIdx.x * BM;
    int tr  = tid >> 4;          // 0..15, row group
    int tc  = tid & 15;          // 0..15, col group

    float acc[8][8];
#pragma unroll
    for (int i = 0; i < 8; i++)
#pragma unroll
        for (int j = 0; j < 8; j++) acc[i][j] = 0.f;

    for (int kt = 0; kt < 2 * DIM; kt += BK) {
        // ---- load A tile (128 rows x 32 k), transposed store As[k][m] ----
#pragma unroll
        for (int i = 0; i < 4; i++) {
            int lin = tid + 256 * i;       // 0..1023
            int row = lin >> 3;            // 0..127
            int kq  = (lin & 7) * 4;       // 0,4,..,28
            int grow = r0 + row;
            int k = kt + kq;
            float4 v = make_float4(0.f, 0.f, 0.f, 0.f);
            if (grow < N) {
                if (k < DIM) {
                    v = *reinterpret_cast<const float4*>(x + (size_t)grow * DIM + k);
                } else {
                    v = *reinterpret_cast<const float4*>(g_agg + (size_t)grow * DIM + (k - DIM));
                    float sc = 1.0f / fmaxf(g_deg[grow], 1.0f);
                    v.x *= sc; v.y *= sc; v.z *= sc; v.w *= sc;
                }
            }
            As[kq + 0][row] = v.x;
            As[kq + 1][row] = v.y;
            As[kq + 2][row] = v.z;
            As[kq + 3][row] = v.w;
        }
        // ---- load B tile: Bs[k][n] = W[n][k] ----
#pragma unroll
        for (int i = 0; i < 4; i++) {
            int lin = tid + 256 * i;
            int n  = lin >> 3;             // 0..127
            int kq = (lin & 7) * 4;
            int k  = kt + kq;
            const float* W = (k < DIM) ? Ws : Wn;
            int kk = (k < DIM) ? k : (k - DIM);
            float4 v = *reinterpret_cast<const float4*>(W + (size_t)n * DIM + kk);
            Bs[kq + 0][n] = v.x;
            Bs[kq + 1][n] = v.y;
            Bs[kq + 2][n] = v.z;
            Bs[kq + 3][n] = v.w;
        }
        __syncthreads();

        // ---- 8x8 micro-tile FFMA ----
#pragma unroll
        for (int kk = 0; kk < BK; kk++) {
            float a[8], b[8];
            *reinterpret_cast<float4*>(a + 0) = *reinterpret_cast<const float4*>(&As[kk][tr * 8 + 0]);
            *reinterpret_cast<float4*>(a + 4) = *reinterpret_cast<const float4*>(&As[kk][tr * 8 + 4]);
            *reinterpret_cast<float4*>(b + 0) = *reinterpret_cast<const float4*>(&Bs[kk][tc * 8 + 0]);
            *reinterpret_cast<float4*>(b + 4) = *reinterpret_cast<const float4*>(&Bs[kk][tc * 8 + 4]);
#pragma unroll
            for (int i = 0; i < 8; i++)
#pragma unroll
                for (int j = 0; j < 8; j++)
                    acc[i][j] += a[i] * b[j];
        }
        __syncthreads();
    }

    // ---- epilogue: bias + relu + store ----
    float bv[8];
#pragma unroll
    for (int j = 0; j < 8; j++) bv[j] = bias[tc * 8 + j];

#pragma unroll
    for (int i = 0; i < 8; i++) {
        int grow = r0 + tr * 8 + i;
        if (grow >= N) continue;
#pragma unroll
        for (int j = 0; j < 8; j += 4) {
            float4 o;
            o.x = fmaxf(acc[i][j + 0] + bv[j + 0], 0.f);
            o.y = fmaxf(acc[i][j + 1] + bv[j + 1], 0.f);
            o.z = fmaxf(acc[i][j + 2] + bv[j + 2], 0.f);
            o.w = fmaxf(acc[i][j + 3] + bv[j + 3], 0.f);
            *reinterpret_cast<float4*>(out + (size_t)grow * DIM + tc * 8 + j) = o;
        }
    }
}

// ---------------------------------------------------------------------------
// Launch
// ---------------------------------------------------------------------------
extern "C" void kernel_launch(void* const* d_in, const int* in_sizes, int n_in,
                              void* d_out, int out_size) {
    const float* x  = (const float*)d_in[0];
    const void*  ei = d_in[1];

    int N = in_sizes[0] / DIM;          // 100000
    int E = in_sizes[1] / 2;            // 800000

    // num_nodes may or may not be serialized as a 1-element input
    int iW = (n_in >= 6 && in_sizes[2] == 1) ? 3 : 2;
    const float* Ws   = (const float*)d_in[iW];
    const float* Wn   = (const float*)d_in[iW + 1];
    const float* bias = (const float*)d_in[iW + 2];
    float* out = (float*)d_out;

    // 1. zero scratch + probe index dtype
    int n_agg4 = (N * DIM) / 4;
    zero_probe_kernel<<<1024, 256>>>((const long long*)ei, n_agg4, N, (long long)N);

    // 2. edge scatter: one warp per undirected edge (8 warps/block)
    int nblocks = (E + 7) / 8;
    scatter_kernel<<<nblocks, 256>>>(x, ei, E, N);

    // 3. fused GEMM + bias + relu
    int gblocks = (N + BM - 1) / BM;
    gemm_kernel<<<gblocks, 256>>>(x, Ws, Wn, bias, out, N);
}

// round 4
// speedup vs baseline: 1.4452x; 1.4452x over previous
#include <cuda_runtime.h>
#include <cuda_bf16.h>
#include <cstdint>

// ---------------------------------------------------------------------------
// GraphSAGE layer on GB300 (sm_103 baseline target -> mma.sync tf32, no tcgen05)
//   agg[d] += x[s] over bidirectional edges; deg[d] += 1
//   out = relu( x @ Ws^T + (agg/max(deg,1)) @ Wn^T + bias )
// N = 100000, in_dim = out_dim = 128, E = 800000 undirected (1.6M directed)
// ---------------------------------------------------------------------------

#define MAXN 100000
#define DIM  128

__device__ __align__(16) float g_agg[(size_t)MAXN * DIM];
__device__ __align__(16) float g_deg[MAXN];
__device__ int g_is64;

__device__ __forceinline__ float to_tf32(float f) {
    float r;
    asm("cvt.rna.tf32.f32 %0, %1;" : "=f"(r) : "f"(f));
    return r;
}

// ---------------------------------------------------------------------------
// Kernel 1: zero agg+deg, probe edge dtype (JAX may emit int32 or int64)
// ---------------------------------------------------------------------------
__global__ void zero_probe_kernel(const long long* __restrict__ ei64,
                                  int n_agg4, int n_deg, long long N) {
    int i = blockIdx.x * blockDim.x + threadIdx.x;
    int stride = gridDim.x * blockDim.x;
    if (i == 0) {
        int is64 = 1;
#pragma unroll
        for (int k = 0; k < 4; k++)
            if ((unsigned long long)ei64[k] >= (unsigned long long)N) is64 = 0;
        g_is64 = is64;
    }
    float4 z = make_float4(0.f, 0.f, 0.f, 0.f);
    float4* agg4 = reinterpret_cast<float4*>(g_agg);
    for (int k = i; k < n_agg4; k += stride) agg4[k] = z;
    for (int k = i; k < n_deg; k += stride) g_deg[k] = 0.f;
}

// ---------------------------------------------------------------------------
// Kernel 2: edge scatter (one warp per undirected edge, red.v4 both dirs)
// ---------------------------------------------------------------------------
__device__ __forceinline__ void red_add_v4(float* dst, float4 v) {
    asm volatile("red.global.add.v4.f32 [%0], {%1, %2, %3, %4};"
                 :: "l"(dst), "f"(v.x), "f"(v.y), "f"(v.z), "f"(v.w) : "memory");
}

__global__ void scatter_kernel(const float* __restrict__ x,
                               const void* __restrict__ ei_raw,
                               int E, int N) {
    int gw = (blockIdx.x * blockDim.x + threadIdx.x) >> 5;
    int lane = threadIdx.x & 31;
    if (gw >= E) return;

    long long s, d;
    if (g_is64) {
        const long long* ei = (const long long*)ei_raw;
        s = ei[gw]; d = ei[(size_t)E + gw];
    } else {
        const int* ei = (const int*)ei_raw;
        s = ei[gw]; d = ei[(size_t)E + gw];
    }
    if ((unsigned long long)s >= (unsigned long long)N ||
        (unsigned long long)d >= (unsigned long long)N) return;

    float4 vs = *reinterpret_cast<const float4*>(x + (size_t)s * DIM + lane * 4);
    red_add_v4(g_agg + (size_t)d * DIM + lane * 4, vs);
    float4 vd = *reinterpret_cast<const float4*>(x + (size_t)d * DIM + lane * 4);
    red_add_v4(g_agg + (size_t)s * DIM + lane * 4, vd);

    if (lane == 0) {
        atomicAdd(&g_deg[d], 1.0f);
        atomicAdd(&g_deg[s], 1.0f);
    }
}

// ---------------------------------------------------------------------------
// Kernel 3: tf32 mma.sync GEMM.  out = relu([x | agg/deg] @ [Ws|Wn]^T + bias)
// CTA: 128 rows x 128 cols, K=256 in 8 chunks of 32.
// 8 warps = 2(m) x 4(n); warp tile 64x32; mma.m16n8k8.
// ---------------------------------------------------------------------------
#define BK   32
#define LDP  36   // smem row stride (floats): (4g+t) mod 32 distinct -> conflict-free

__device__ __forceinline__ void mma_tf32(float* c, const uint32_t* a, const uint32_t* b) {
    asm volatile(
        "mma.sync.aligned.m16n8k8.row.col.f32.tf32.tf32.f32 "
        "{%0,%1,%2,%3}, {%4,%5,%6,%7}, {%8,%9}, {%0,%1,%2,%3};"
        : "+f"(c[0]), "+f"(c[1]), "+f"(c[2]), "+f"(c[3])
        : "r"(a[0]), "r"(a[1]), "r"(a[2]), "r"(a[3]), "r"(b[0]), "r"(b[1]));
}

__global__ __launch_bounds__(256) void gemm_mma_kernel(
    const float* __restrict__ x,
    const float* __restrict__ Ws,
    const float* __restrict__ Wn,
    const float* __restrict__ bias,
    float* __restrict__ out,
    int N)
{
    __shared__ float As[128][LDP];
    __shared__ float Bs[128][LDP];

    int tid  = threadIdx.x;
    int wid  = tid >> 5;
    int lane = tid & 31;
    int g    = lane >> 2;        // group id 0..7
    int t    = lane & 3;         // thread in group 0..3
    int wm   = wid >> 2;         // 0..1 -> m offset wm*64
    int wn   = wid & 3;          // 0..3 -> n offset wn*32
    int r0   = blockIdx.x * 128;

    float acc[4][4][4];
#pragma unroll
    for (int mf = 0; mf < 4; mf++)
#pragma unroll
        for (int nf = 0; nf < 4; nf++)
#pragma unroll
            for (int i = 0; i < 4; i++) acc[mf][nf][i] = 0.f;

    for (int c = 0; c < 8; c++) {
        // ---- A tile: 128 rows x 32 k of [x | agg/deg] ----
#pragma unroll
        for (int i = 0; i < 4; i++) {
            int idx  = tid + 256 * i;      // 0..1023 float4 slots
            int row  = idx >> 3;           // 0..127
            int q    = idx & 7;            // float4 within 32-k row
            int node = r0 + row;
            int k    = c * 32 + q * 4;
            float4 v = make_float4(0.f, 0.f, 0.f, 0.f);
            if (node < N) {
                if (k < DIM) {
                    v = *reinterpret_cast<const float4*>(x + (size_t)node * DIM + k);
                } else {
                    v = *reinterpret_cast<const float4*>(g_agg + (size_t)node * DIM + (k - DIM));
                    float sc = 1.0f / fmaxf(g_deg[node], 1.0f);
                    v.x *= sc; v.y *= sc; v.z *= sc; v.w *= sc;
                }
            }
            v.x = to_tf32(v.x); v.y = to_tf32(v.y); v.z = to_tf32(v.z); v.w = to_tf32(v.w);
            *reinterpret_cast<float4*>(&As[row][q * 4]) = v;
        }
        // ---- B tile: 128 n x 32 k of [Ws|Wn][n][k] ----
#pragma unroll
        for (int i = 0; i < 4; i++) {
            int idx = tid + 256 * i;
            int n   = idx >> 3;
            int q   = idx & 7;
            int k   = c * 32 + q * 4;
            const float* W = (k < DIM) ? Ws : Wn;
            int kk = k & (DIM - 1);
            float4 v = *reinterpret_cast<const float4*>(W + (size_t)n * DIM + kk);
            v.x = to_tf32(v.x); v.y = to_tf32(v.y); v.z = to_tf32(v.z); v.w = to_tf32(v.w);
            *reinterpret_cast<float4*>(&Bs[n][q * 4]) = v;
        }
        __syncthreads();

        // ---- 4 K-steps of 8 ----
#pragma unroll
        for (int s = 0; s < 4; s++) {
            int k0 = s * 8;
            uint32_t a[4][4];
#pragma unroll
            for (int mf = 0; mf < 4; mf++) {
                int m0 = wm * 64 + mf * 16;
                a[mf][0] = __float_as_uint(As[m0 + g][k0 + t]);
                a[mf][1] = __float_as_uint(As[m0 + g + 8][k0 + t]);
                a[mf][2] = __float_as_uint(As[m0 + g][k0 + t + 4]);
                a[mf][3] = __float_as_uint(As[m0 + g + 8][k0 + t + 4]);
            }
            uint32_t b[4][2];
#pragma unroll
            for (int nf = 0; nf < 4; nf++) {
                int n0 = wn * 32 + nf * 8;
                b[nf][0] = __float_as_uint(Bs[n0 + g][k0 + t]);
                b[nf][1] = __float_as_uint(Bs[n0 + g][k0 + t + 4]);
            }
#pragma unroll
            for (int mf = 0; mf < 4; mf++)
#pragma unroll
                for (int nf = 0; nf < 4; nf++)
                    mma_tf32(acc[mf][nf], a[mf], b[nf]);
        }
        __syncthreads();
    }

    // ---- epilogue: bias + relu, float2 stores ----
#pragma unroll
    for (int mf = 0; mf < 4; mf++) {
        int row0 = r0 + wm * 64 + mf * 16 + g;
        int row1 = row0 + 8;
#pragma unroll
        for (int nf = 0; nf < 4; nf++) {
            int col = wn * 32 + nf * 8 + 2 * t;
            float2 bv = *reinterpret_cast<const float2*>(bias + col);
            if (row0 < N) {
                float2 o;
                o.x = fmaxf(acc[mf][nf][0] + bv.x, 0.f);
                o.y = fmaxf(acc[mf][nf][1] + bv.y, 0.f);
                *reinterpret_cast<float2*>(out + (size_t)row0 * DIM + col) = o;
            }
            if (row1 < N) {
                float2 o;
                o.x = fmaxf(acc[mf][nf][2] + bv.x, 0.f);
                o.y = fmaxf(acc[mf][nf][3] + bv.y, 0.f);
                *reinterpret_cast<float2*>(out + (size_t)row1 * DIM + col) = o;
            }
        }
    }
}

// ---------------------------------------------------------------------------
// Launch
// ---------------------------------------------------------------------------
extern "C" void kernel_launch(void* const* d_in, const int* in_sizes, int n_in,
                              void* d_out, int out_size) {
    const float* x  = (const float*)d_in[0];
    const void*  ei = d_in[1];

    int N = in_sizes[0] / DIM;          // 100000
    int E = in_sizes[1] / 2;            // 800000

    int iW = (n_in >= 6 && in_sizes[2] == 1) ? 3 : 2;
    const float* Ws   = (const float*)d_in[iW];
    const float* Wn   = (const float*)d_in[iW + 1];
    const float* bias = (const float*)d_in[iW + 2];
    float* out = (float*)d_out;

    int n_agg4 = (N * DIM) / 4;
    zero_probe_kernel<<<1024, 256>>>((const long long*)ei, n_agg4, N, (long long)N);

    int nblocks = (E + 7) / 8;
    scatter_kernel<<<nblocks, 256>>>(x, ei, E, N);

    int gblocks = (N + 127) / 128;
    gemm_mma_kernel<<<gblocks, 256>>>(x, Ws, Wn, bias, out, N);
}

// round 5
// speedup vs baseline: 1.7280x; 1.1957x over previous
#include <cuda_runtime.h>
#include <cuda_bf16.h>
#include <cstdint>

// ---------------------------------------------------------------------------
// GraphSAGE layer on GB300 (sm_103 baseline -> mma.sync tf32)
// CSR two-phase aggregation (no feature atomics) + tf32 tensor-core GEMM.
//   agg[i] = mean over neighbors (bidirectional) of x
//   out = relu( x @ Ws^T + agg @ Wn^T + bias )
// N = 100000, in_dim = out_dim = 128, E = 800000 undirected (1.6M directed)
// ---------------------------------------------------------------------------

#define MAXN 100000
#define MAXE 800000
#define DIM  128

__device__ __align__(16) float g_agg[(size_t)MAXN * DIM];   // normalized agg
__device__ int g_degI[MAXN];
__device__ int g_rowStart[MAXN];
__device__ int g_wpos[MAXN];
__device__ int g_nbr[2 * MAXE];
__device__ int g_cursor;
__device__ int g_is64;

__device__ __forceinline__ float to_tf32(float f) {
    float r;
    asm("cvt.rna.tf32.f32 %0, %1;" : "=f"(r) : "f"(f));
    return r;
}

// ---------------------------------------------------------------------------
// Kernel A: zero degI + cursor, probe edge dtype (JAX may emit int32/int64)
// ---------------------------------------------------------------------------
__global__ void init_probe_kernel(const long long* __restrict__ ei64,
                                  int n_deg, long long N) {
    int i = blockIdx.x * blockDim.x + threadIdx.x;
    int stride = gridDim.x * blockDim.x;
    if (i == 0) {
        int is64 = 1;
#pragma unroll
        for (int k = 0; k < 4; k++)
            if ((unsigned long long)ei64[k] >= (unsigned long long)N) is64 = 0;
        g_is64 = is64;
        g_cursor = 0;
    }
    for (int k = i; k < n_deg; k += stride) g_degI[k] = 0;
}

// ---------------------------------------------------------------------------
// helpers: load one input edge with dtype branch + bounds guard
// ---------------------------------------------------------------------------
__device__ __forceinline__ bool load_edge(const void* ei_raw, int E, int N,
                                          int e, int& s, int& d) {
    long long sl, dl;
    if (g_is64) {
        const long long* ei = (const long long*)ei_raw;
        sl = ei[e]; dl = ei[(size_t)E + e];
    } else {
        const int* ei = (const int*)ei_raw;
        sl = ei[e]; dl = ei[(size_t)E + e];
    }
    if ((unsigned long long)sl >= (unsigned long long)N ||
        (unsigned long long)dl >= (unsigned long long)N) return false;
    s = (int)sl; d = (int)dl;
    return true;
}

// ---------------------------------------------------------------------------
// Kernel B: count degrees (both directions)
// ---------------------------------------------------------------------------
__global__ void count_kernel(const void* __restrict__ ei_raw, int E, int N) {
    int e = blockIdx.x * blockDim.x + threadIdx.x;
    if (e >= E) return;
    int s, d;
    if (!load_edge(ei_raw, E, N, e, s, d)) return;
    atomicAdd(&g_degI[s], 1);
    atomicAdd(&g_degI[d], 1);
}

// ---------------------------------------------------------------------------
// Kernel C: allocate contiguous segments (order irrelevant -> atomic cursor)
// ---------------------------------------------------------------------------
__global__ void alloc_kernel(int N) {
    int i = blockIdx.x * blockDim.x + threadIdx.x;
    if (i >= N) return;
    int deg = g_degI[i];
    int start = atomicAdd(&g_cursor, deg);
    g_rowStart[i] = start;
    g_wpos[i] = start;
}

// ---------------------------------------------------------------------------
// Kernel D: fill adjacency
// ---------------------------------------------------------------------------
__global__ void fill_kernel(const void* __restrict__ ei_raw, int E, int N) {
    int e = blockIdx.x * blockDim.x + threadIdx.x;
    if (e >= E) return;
    int s, d;
    if (!load_edge(ei_raw, E, N, e, s, d)) return;
    int p0 = atomicAdd(&g_wpos[d], 1);
    g_nbr[p0] = s;
    int p1 = atomicAdd(&g_wpos[s], 1);
    g_nbr[p1] = d;
}

// ---------------------------------------------------------------------------
// Kernel E: gather. One warp per node: agg[i] = sum(x[nbr]) / max(deg,1)
// Unroll x4 for memory-level parallelism.
// ---------------------------------------------------------------------------
__global__ void gather_kernel(const float* __restrict__ x, int N) {
    int warp = (blockIdx.x * blockDim.x + threadIdx.x) >> 5;
    int lane = threadIdx.x & 31;
    if (warp >= N) return;

    int start = g_rowStart[warp];
    int deg   = g_degI[warp];
    int end   = start + deg;

    const float4* x4 = reinterpret_cast<const float4*>(x);
    float4 acc = make_float4(0.f, 0.f, 0.f, 0.f);

    int j = start;
    for (; j + 4 <= end; j += 4) {
        int n0 = g_nbr[j], n1 = g_nbr[j + 1], n2 = g_nbr[j + 2], n3 = g_nbr[j + 3];
        float4 v0 = x4[(size_t)n0 * 32 + lane];
        float4 v1 = x4[(size_t)n1 * 32 + lane];
        float4 v2 = x4[(size_t)n2 * 32 + lane];
        float4 v3 = x4[(size_t)n3 * 32 + lane];
        acc.x += v0.x + v1.x + v2.x + v3.x;
        acc.y += v0.y + v1.y + v2.y + v3.y;
        acc.z += v0.z + v1.z + v2.z + v3.z;
        acc.w += v0.w + v1.w + v2.w + v3.w;
    }
    for (; j < end; j++) {
        int n = g_nbr[j];
        float4 v = x4[(size_t)n * 32 + lane];
        acc.x += v.x; acc.y += v.y; acc.z += v.z; acc.w += v.w;
    }

    float inv = 1.0f / fmaxf((float)deg, 1.0f);
    acc.x *= inv; acc.y *= inv; acc.z *= inv; acc.w *= inv;
    reinterpret_cast<float4*>(g_agg)[(size_t)warp * 32 + lane] = acc;
}

// ---------------------------------------------------------------------------
// Kernel F: tf32 mma.sync GEMM.  out = relu([x | agg] @ [Ws|Wn]^T + bias)
// CTA: 128x128, K=256 in 8 chunks of 32. 8 warps = 2(m) x 4(n), warp 64x32.
// ---------------------------------------------------------------------------
#define LDP 36   // smem row stride (floats), conflict-free fragment reads

__device__ __forceinline__ void mma_tf32(float* c, const uint32_t* a, const uint32_t* b) {
    asm volatile(
        "mma.sync.aligned.m16n8k8.row.col.f32.tf32.tf32.f32 "
        "{%0,%1,%2,%3}, {%4,%5,%6,%7}, {%8,%9}, {%0,%1,%2,%3};"
        : "+f"(c[0]), "+f"(c[1]), "+f"(c[2]), "+f"(c[3])
        : "r"(a[0]), "r"(a[1]), "r"(a[2]), "r"(a[3]), "r"(b[0]), "r"(b[1]));
}

__global__ __launch_bounds__(256) void gemm_mma_kernel(
    const float* __restrict__ x,
    const float* __restrict__ Ws,
    const float* __restrict__ Wn,
    const float* __restrict__ bias,
    float* __restrict__ out,
    int N)
{
    __shared__ float As[128][LDP];
    __shared__ float Bs[128][LDP];

    int tid  = threadIdx.x;
    int wid  = tid >> 5;
    int lane = tid & 31;
    int g    = lane >> 2;
    int t    = lane & 3;
    int wm   = wid >> 2;
    int wn   = wid & 3;
    int r0   = blockIdx.x * 128;

    float acc[4][4][4];
#pragma unroll
    for (int mf = 0; mf < 4; mf++)
#pragma unroll
        for (int nf = 0; nf < 4; nf++)
#pragma unroll
            for (int i = 0; i < 4; i++) acc[mf][nf][i] = 0.f;

    for (int c = 0; c < 8; c++) {
        // ---- A tile: 128 rows x 32 k of [x | agg] ----
#pragma unroll
        for (int i = 0; i < 4; i++) {
            int idx  = tid + 256 * i;
            int row  = idx >> 3;
            int q    = idx & 7;
            int node = r0 + row;
            int k    = c * 32 + q * 4;
            float4 v = make_float4(0.f, 0.f, 0.f, 0.f);
            if (node < N) {
                const float* src = (k < DIM) ? (x + (size_t)node * DIM + k)
                                             : (g_agg + (size_t)node * DIM + (k - DIM));
                v = *reinterpret_cast<const float4*>(src);
            }
            v.x = to_tf32(v.x); v.y = to_tf32(v.y); v.z = to_tf32(v.z); v.w = to_tf32(v.w);
            *reinterpret_cast<float4*>(&As[row][q * 4]) = v;
        }
        // ---- B tile: 128 n x 32 k of [Ws|Wn][n][k] ----
#pragma unroll
        for (int i = 0; i < 4; i++) {
            int idx = tid + 256 * i;
            int n   = idx >> 3;
            int q   = idx & 7;
            int k   = c * 32 + q * 4;
            const float* W = (k < DIM) ? Ws : Wn;
            int kk = k & (DIM - 1);
            float4 v = *reinterpret_cast<const float4*>(W + (size_t)n * DIM + kk);
            v.x = to_tf32(v.x); v.y = to_tf32(v.y); v.z = to_tf32(v.z); v.w = to_tf32(v.w);
            *reinterpret_cast<float4*>(&Bs[n][q * 4]) = v;
        }
        __syncthreads();

#pragma unroll
        for (int s = 0; s < 4; s++) {
            int k0 = s * 8;
            uint32_t a[4][4];
#pragma unroll
            for (int mf = 0; mf < 4; mf++) {
                int m0 = wm * 64 + mf * 16;
                a[mf][0] = __float_as_uint(As[m0 + g][k0 + t]);
                a[mf][1] = __float_as_uint(As[m0 + g + 8][k0 + t]);
                a[mf][2] = __float_as_uint(As[m0 + g][k0 + t + 4]);
                a[mf][3] = __float_as_uint(As[m0 + g + 8][k0 + t + 4]);
            }
            uint32_t b[4][2];
#pragma unroll
            for (int nf = 0; nf < 4; nf++) {
                int n0 = wn * 32 + nf * 8;
                b[nf][0] = __float_as_uint(Bs[n0 + g][k0 + t]);
                b[nf][1] = __float_as_uint(Bs[n0 + g][k0 + t + 4]);
            }
#pragma unroll
            for (int mf = 0; mf < 4; mf++)
#pragma unroll
                for (int nf = 0; nf < 4; nf++)
                    mma_tf32(acc[mf][nf], a[mf], b[nf]);
        }
        __syncthreads();
    }

#pragma unroll
    for (int mf = 0; mf < 4; mf++) {
        int row0 = r0 + wm * 64 + mf * 16 + g;
        int row1 = row0 + 8;
#pragma unroll
        for (int nf = 0; nf < 4; nf++) {
            int col = wn * 32 + nf * 8 + 2 * t;
            float2 bv = *reinterpret_cast<const float2*>(bias + col);
            if (row0 < N) {
                float2 o;
                o.x = fmaxf(acc[mf][nf][0] + bv.x, 0.f);
                o.y = fmaxf(acc[mf][nf][1] + bv.y, 0.f);
                *reinterpret_cast<float2*>(out + (size_t)row0 * DIM + col) = o;
            }
            if (row1 < N) {
                float2 o;
                o.x = fmaxf(acc[mf][nf][2] + bv.x, 0.f);
                o.y = fmaxf(acc[mf][nf][3] + bv.y, 0.f);
                *reinterpret_cast<float2*>(out + (size_t)row1 * DIM + col) = o;
            }
        }
    }
}

// ---------------------------------------------------------------------------
// Launch
// ---------------------------------------------------------------------------
extern "C" void kernel_launch(void* const* d_in, const int* in_sizes, int n_in,
                              void* d_out, int out_size) {
    const float* x  = (const float*)d_in[0];
    const void*  ei = d_in[1];

    int N = in_sizes[0] / DIM;          // 100000
    int E = in_sizes[1] / 2;            // 800000

    int iW = (n_in >= 6 && in_sizes[2] == 1) ? 3 : 2;
    const float* Ws   = (const float*)d_in[iW];
    const float* Wn   = (const float*)d_in[iW + 1];
    const float* bias = (const float*)d_in[iW + 2];
    float* out = (float*)d_out;

    init_probe_kernel<<<512, 256>>>((const long long*)ei, N, (long long)N);

    int eblocks = (E + 255) / 256;
    count_kernel<<<eblocks, 256>>>(ei, E, N);

    alloc_kernel<<<(N + 255) / 256, 256>>>(N);

    fill_kernel<<<eblocks, 256>>>(ei, E, N);

    // gather: one warp per node, 8 warps per block
    gather_kernel<<<(N + 7) / 8, 256>>>(x, N);

    int gblocks = (N + 127) / 128;
    gemm_mma_kernel<<<gblocks, 256>>>(x, Ws, Wn, bias, out, N);
}

// round 6
// speedup vs baseline: 2.2315x; 1.2914x over previous
#include <cuda_runtime.h>
#include <cuda_bf16.h>
#include <cstdint>

// ---------------------------------------------------------------------------
// GraphSAGE layer on GB300 (sm_103 baseline -> mma.sync tf32)
// CSR two-phase aggregation (atomic-free fill) + tf32 tensor-core GEMM with
// register double buffering.
//   agg[i] = mean over neighbors (bidirectional) of x
//   out = relu( x @ Ws^T + agg @ Wn^T + bias )
// N = 100000, in_dim = out_dim = 128, E = 800000 undirected (1.6M directed)
// ---------------------------------------------------------------------------

#define MAXN 100000
#define MAXE 800000
#define DIM  128

__device__ __align__(16) float g_agg[(size_t)MAXN * DIM];   // normalized agg
__device__ int g_degI[MAXN];
__device__ int g_rowStart[MAXN];
__device__ int g_nbr[2 * MAXE];
__device__ int g_slotS[MAXE];
__device__ int g_slotD[MAXE];
__device__ int g_cursor;
__device__ int g_is64;

__device__ __forceinline__ float to_tf32(float f) {
    float r;
    asm("cvt.rna.tf32.f32 %0, %1;" : "=f"(r) : "f"(f));
    return r;
}

// ---------------------------------------------------------------------------
// Kernel A: zero degI + cursor, probe edge dtype (JAX may emit int32/int64)
// ---------------------------------------------------------------------------
__global__ void init_probe_kernel(const long long* __restrict__ ei64,
                                  int n_deg, long long N) {
    int i = blockIdx.x * blockDim.x + threadIdx.x;
    int stride = gridDim.x * blockDim.x;
    if (i == 0) {
        int is64 = 1;
#pragma unroll
        for (int k = 0; k < 4; k++)
            if ((unsigned long long)ei64[k] >= (unsigned long long)N) is64 = 0;
        g_is64 = is64;
        g_cursor = 0;
    }
    for (int k = i; k < n_deg; k += stride) g_degI[k] = 0;
}

__device__ __forceinline__ bool load_edge(const void* ei_raw, int E, int N,
                                          int e, int& s, int& d) {
    long long sl, dl;
    if (g_is64) {
        const long long* ei = (const long long*)ei_raw;
        sl = ei[e]; dl = ei[(size_t)E + e];
    } else {
        const int* ei = (const int*)ei_raw;
        sl = ei[e]; dl = ei[(size_t)E + e];
    }
    if ((unsigned long long)sl >= (unsigned long long)N ||
        (unsigned long long)dl >= (unsigned long long)N) return false;
    s = (int)sl; d = (int)dl;
    return true;
}

// ---------------------------------------------------------------------------
// Kernel B: count degrees; atomic return value = unique slot per endpoint
// ---------------------------------------------------------------------------
__global__ void count_kernel(const void* __restrict__ ei_raw, int E, int N) {
    int e = blockIdx.x * blockDim.x + threadIdx.x;
    if (e >= E) return;
    int s, d;
    if (!load_edge(ei_raw, E, N, e, s, d)) { g_slotS[e] = -1; return; }
    g_slotS[e] = atomicAdd(&g_degI[s], 1);
    g_slotD[e] = atomicAdd(&g_degI[d], 1);
}

// ---------------------------------------------------------------------------
// Kernel C: allocate segments — warp-aggregated scan, 1 atomic per warp
// ---------------------------------------------------------------------------
__global__ void alloc_kernel(int N) {
    int i = blockIdx.x * blockDim.x + threadIdx.x;
    int lane = threadIdx.x & 31;
    int deg = (i < N) ? g_degI[i] : 0;
    int sum = deg;
#pragma unroll
    for (int off = 1; off < 32; off <<= 1) {
        int v = __shfl_up_sync(0xFFFFFFFF, sum, off);
        if (lane >= off) sum += v;
    }
    int total = __shfl_sync(0xFFFFFFFF, sum, 31);
    int base = 0;
    if (lane == 31) base = atomicAdd(&g_cursor, total);
    base = __shfl_sync(0xFFFFFFFF, base, 31);
    if (i < N) g_rowStart[i] = base + sum - deg;
}

// ---------------------------------------------------------------------------
// Kernel D: fill adjacency — no atomics (slots precomputed by count)
// ---------------------------------------------------------------------------
__global__ void fill_kernel(const void* __restrict__ ei_raw, int E, int N) {
    int e = blockIdx.x * blockDim.x + threadIdx.x;
    if (e >= E) return;
    int ps = g_slotS[e];
    if (ps < 0) return;                    // bounds-failed edge
    int s, d;
    (void)load_edge(ei_raw, E, N, e, s, d);
    int pd = g_slotD[e];
    g_nbr[g_rowStart[s] + ps] = d;
    g_nbr[g_rowStart[d] + pd] = s;
}

// ---------------------------------------------------------------------------
// Kernel E: gather. One warp per node: agg[i] = sum(x[nbr]) / max(deg,1)
// Unroll x8 for memory-level parallelism.
// ---------------------------------------------------------------------------
__global__ void gather_kernel(const float* __restrict__ x, int N) {
    int warp = (blockIdx.x * blockDim.x + threadIdx.x) >> 5;
    int lane = threadIdx.x & 31;
    if (warp >= N) return;

    int start = g_rowStart[warp];
    int deg   = g_degI[warp];
    int end   = start + deg;

    const float4* x4 = reinterpret_cast<const float4*>(x);
    float4 acc = make_float4(0.f, 0.f, 0.f, 0.f);

    int j = start;
    for (; j + 8 <= end; j += 8) {
        int n[8];
#pragma unroll
        for (int u = 0; u < 8; u++) n[u] = g_nbr[j + u];
        float4 v[8];
#pragma unroll
        for (int u = 0; u < 8; u++) v[u] = x4[(size_t)n[u] * 32 + lane];
#pragma unroll
        for (int u = 0; u < 8; u++) {
            acc.x += v[u].x; acc.y += v[u].y; acc.z += v[u].z; acc.w += v[u].w;
        }
    }
    for (; j < end; j++) {
        int n = g_nbr[j];
        float4 v = x4[(size_t)n * 32 + lane];
        acc.x += v.x; acc.y += v.y; acc.z += v.z; acc.w += v.w;
    }

    float inv = 1.0f / fmaxf((float)deg, 1.0f);
    acc.x *= inv; acc.y *= inv; acc.z *= inv; acc.w *= inv;
    reinterpret_cast<float4*>(g_agg)[(size_t)warp * 32 + lane] = acc;
}

// ---------------------------------------------------------------------------
// Kernel F: tf32 mma.sync GEMM, register double-buffered.
// out = relu([x | agg] @ [Ws|Wn]^T + bias)
// CTA: 128x128, K=256 in 8 chunks of 32. 8 warps = 2(m) x 4(n), warp 64x32.
// ---------------------------------------------------------------------------
#define LDP 36

__device__ __forceinline__ void mma_tf32(float* c, const uint32_t* a, const uint32_t* b) {
    asm volatile(
        "mma.sync.aligned.m16n8k8.row.col.f32.tf32.tf32.f32 "
        "{%0,%1,%2,%3}, {%4,%5,%6,%7}, {%8,%9}, {%0,%1,%2,%3};"
        : "+f"(c[0]), "+f"(c[1]), "+f"(c[2]), "+f"(c[3])
        : "r"(a[0]), "r"(a[1]), "r"(a[2]), "r"(a[3]), "r"(b[0]), "r"(b[1]));
}

__global__ __launch_bounds__(256) void gemm_mma_kernel(
    const float* __restrict__ x,
    const float* __restrict__ Ws,
    const float* __restrict__ Wn,
    const float* __restrict__ bias,
    float* __restrict__ out,
    int N)
{
    __shared__ float As[128][LDP];
    __shared__ float Bs[128][LDP];

    int tid  = threadIdx.x;
    int wid  = tid >> 5;
    int lane = tid & 31;
    int g    = lane >> 2;
    int t    = lane & 3;
    int wm   = wid >> 2;
    int wn   = wid & 3;
    int r0   = blockIdx.x * 128;

    // per-thread load coordinates (fixed across chunks)
    int arow[4], aq[4], anode[4];
    int brow[4], bq[4];
#pragma unroll
    for (int i = 0; i < 4; i++) {
        int idx = tid + 256 * i;
        arow[i] = idx >> 3;  aq[i] = idx & 7;  anode[i] = r0 + arow[i];
        brow[i] = idx >> 3;  bq[i] = idx & 7;
    }

    float acc[4][4][4];
#pragma unroll
    for (int mf = 0; mf < 4; mf++)
#pragma unroll
        for (int nf = 0; nf < 4; nf++)
#pragma unroll
            for (int i = 0; i < 4; i++) acc[mf][nf][i] = 0.f;

    float4 ra[4], rb[4];

    // load chunk 0
#pragma unroll
    for (int i = 0; i < 4; i++) {
        int k = aq[i] * 4;                          // chunk 0: k in [0,32)
        ra[i] = (anode[i] < N)
            ? *reinterpret_cast<const float4*>(x + (size_t)anode[i] * DIM + k)
            : make_float4(0.f, 0.f, 0.f, 0.f);
        rb[i] = *reinterpret_cast<const float4*>(Ws + (size_t)brow[i] * DIM + bq[i] * 4);
    }

    for (int c = 0; c < 8; c++) {
        // ---- store current chunk regs -> smem (with tf32 round) ----
#pragma unroll
        for (int i = 0; i < 4; i++) {
            float4 v = ra[i];
            v.x = to_tf32(v.x); v.y = to_tf32(v.y); v.z = to_tf32(v.z); v.w = to_tf32(v.w);
            *reinterpret_cast<float4*>(&As[arow[i]][aq[i] * 4]) = v;
            float4 w = rb[i];
            w.x = to_tf32(w.x); w.y = to_tf32(w.y); w.z = to_tf32(w.z); w.w = to_tf32(w.w);
            *reinterpret_cast<float4*>(&Bs[brow[i]][bq[i] * 4]) = w;
        }
        __syncthreads();

        // ---- prefetch next chunk into regs (overlaps with MMA below) ----
        if (c < 7) {
            int cn = c + 1;
#pragma unroll
            for (int i = 0; i < 4; i++) {
                int k = cn * 32 + aq[i] * 4;
                if (anode[i] < N) {
                    const float* src = (k < DIM)
                        ? (x + (size_t)anode[i] * DIM + k)
                        : (g_agg + (size_t)anode[i] * DIM + (k - DIM));
                    ra[i] = *reinterpret_cast<const float4*>(src);
                } else {
                    ra[i] = make_float4(0.f, 0.f, 0.f, 0.f);
                }
                const float* W = (k < DIM) ? Ws : Wn;
                int kk = k & (DIM - 1);
                rb[i] = *reinterpret_cast<const float4*>(W + (size_t)brow[i] * DIM + kk);
            }
        }

        // ---- MMA over smem chunk ----
#pragma unroll
        for (int s = 0; s < 4; s++) {
            int k0 = s * 8;
            uint32_t a[4][4];
#pragma unroll
            for (int mf = 0; mf < 4; mf++) {
                int m0 = wm * 64 + mf * 16;
                a[mf][0] = __float_as_uint(As[m0 + g][k0 + t]);
                a[mf][1] = __float_as_uint(As[m0 + g + 8][k0 + t]);
                a[mf][2] = __float_as_uint(As[m0 + g][k0 + t + 4]);
                a[mf][3] = __float_as_uint(As[m0 + g + 8][k0 + t + 4]);
            }
            uint32_t b[4][2];
#pragma unroll
            for (int nf = 0; nf < 4; nf++) {
                int n0 = wn * 32 + nf * 8;
                b[nf][0] = __float_as_uint(Bs[n0 + g][k0 + t]);
                b[nf][1] = __float_as_uint(Bs[n0 + g][k0 + t + 4]);
            }
#pragma unroll
            for (int mf = 0; mf < 4; mf++)
#pragma unroll
                for (int nf = 0; nf < 4; nf++)
                    mma_tf32(acc[mf][nf], a[mf], b[nf]);
        }
        __syncthreads();
    }

    // ---- epilogue: bias + relu ----
#pragma unroll
    for (int mf = 0; mf < 4; mf++) {
        int row0 = r0 + wm * 64 + mf * 16 + g;
        int row1 = row0 + 8;
#pragma unroll
        for (int nf = 0; nf < 4; nf++) {
            int col = wn * 32 + nf * 8 + 2 * t;
            float2 bv = *reinterpret_cast<const float2*>(bias + col);
            if (row0 < N) {
                float2 o;
                o.x = fmaxf(acc[mf][nf][0] + bv.x, 0.f);
                o.y = fmaxf(acc[mf][nf][1] + bv.y, 0.f);
                *reinterpret_cast<float2*>(out + (size_t)row0 * DIM + col) = o;
            }
            if (row1 < N) {
                float2 o;
                o.x = fmaxf(acc[mf][nf][2] + bv.x, 0.f);
                o.y = fmaxf(acc[mf][nf][3] + bv.y, 0.f);
                *reinterpret_cast<float2*>(out + (size_t)row1 * DIM + col) = o;
            }
        }
    }
}

// ---------------------------------------------------------------------------
// Launch
// ---------------------------------------------------------------------------
extern "C" void kernel_launch(void* const* d_in, const int* in_sizes, int n_in,
                              void* d_out, int out_size) {
    const float* x  = (const float*)d_in[0];
    const void*  ei = d_in[1];

    int N = in_sizes[0] / DIM;          // 100000
    int E = in_sizes[1] / 2;            // 800000

    int iW = (n_in >= 6 && in_sizes[2] == 1) ? 3 : 2;
    const float* Ws   = (const float*)d_in[iW];
    const float* Wn   = (const float*)d_in[iW + 1];
    const float* bias = (const float*)d_in[iW + 2];
    float* out = (float*)d_out;

    init_probe_kernel<<<512, 256>>>((const long long*)ei, N, (long long)N);

    int eblocks = (E + 255) / 256;
    count_kernel<<<eblocks, 256>>>(ei, E, N);

    alloc_kernel<<<(N + 255) / 256, 256>>>(N);

    fill_kernel<<<eblocks, 256>>>(ei, E, N);

    gather_kernel<<<(N + 7) / 8, 256>>>(x, N);

    int gblocks = (N + 127) / 128;
    gemm_mma_kernel<<<gblocks, 256>>>(x, Ws, Wn, bias, out, N);
}

// round 8
// speedup vs baseline: 2.8338x; 1.2699x over previous
#include <cuda_runtime.h>
#include <cuda_fp16.h>
#include <cstdint>

// ---------------------------------------------------------------------------
// GraphSAGE layer on GB300 (sm_103 baseline -> mma.sync fp16/fp32-acc)
// CSR two-phase aggregation over fp16 features + fp16 tensor-core GEMM.
// fp16 mantissa (11 bit) == tf32 mantissa precision, so this loses nothing
// vs the previous tf32 kernel while halving all feature traffic.
//   agg[i] = mean over neighbors (bidirectional) of x
//   out = relu( x @ Ws^T + agg @ Wn^T + bias )   (fp32 out)
// N = 100000, in_dim = out_dim = 128, E = 800000 undirected (1.6M directed)
// ---------------------------------------------------------------------------

#define MAXN 100000
#define MAXE 800000
#define DIM  128

__device__ __align__(16) __half g_xh [(size_t)MAXN * DIM];   // fp16 x
__device__ __align__(16) __half g_ah [(size_t)MAXN * DIM];   // fp16 agg (normalized)
__device__ __align__(16) __half g_wh [128 * 256];            // fused [Ws|Wn], row n, k 0..255
__device__ int g_degI[MAXN];
__device__ int g_rowStart[MAXN];
__device__ int g_nbr[2 * MAXE];
__device__ int g_slotS[MAXE];
__device__ int g_slotD[MAXE];
__device__ int g_cursor;
__device__ int g_is64;

// bit-cast helpers (no intrinsic exists for half2<->uint)
__device__ __forceinline__ uint32_t h2_to_u32(__half2 h) {
    uint32_t u;
    *reinterpret_cast<__half2*>(&u) = h;
    return u;
}
__device__ __forceinline__ __half2 u32_to_h2(uint32_t u) {
    return *reinterpret_cast<__half2*>(&u);
}

// ---------------------------------------------------------------------------
// Kernel A: zero degI + cursor, probe edge dtype (JAX may emit int32/int64)
// ---------------------------------------------------------------------------
__global__ void init_probe_kernel(const long long* __restrict__ ei64,
                                  int n_deg, long long N) {
    int i = blockIdx.x * blockDim.x + threadIdx.x;
    int stride = gridDim.x * blockDim.x;
    if (i == 0) {
        int is64 = 1;
#pragma unroll
        for (int k = 0; k < 4; k++)
            if ((unsigned long long)ei64[k] >= (unsigned long long)N) is64 = 0;
        g_is64 = is64;
        g_cursor = 0;
    }
    for (int k = i; k < n_deg; k += stride) g_degI[k] = 0;
}

// ---------------------------------------------------------------------------
// Kernel A2: convert x and weights to fp16 (weights fused [Ws|Wn])
// ---------------------------------------------------------------------------
__global__ void convert_kernel(const float* __restrict__ x,
                               const float* __restrict__ Ws,
                               const float* __restrict__ Wn, int N) {
    int i = blockIdx.x * blockDim.x + threadIdx.x;
    int stride = gridDim.x * blockDim.x;
    const float4* x4 = reinterpret_cast<const float4*>(x);
    uint2* xh = reinterpret_cast<uint2*>(g_xh);
    int total = N * (DIM / 4);
    for (int k = i; k < total; k += stride) {
        float4 v = x4[k];
        uint2 o;
        o.x = h2_to_u32(__floats2half2_rn(v.x, v.y));
        o.y = h2_to_u32(__floats2half2_rn(v.z, v.w));
        xh[k] = o;
    }
    uint2* wh = reinterpret_cast<uint2*>(g_wh);
    int wtotal = 128 * 256 / 4;
    for (int k = i; k < wtotal; k += stride) {
        int n = (k * 4) >> 8;
        int c = (k * 4) & 255;
        const float* W = (c < 128) ? (Ws + (size_t)n * 128 + c)
                                   : (Wn + (size_t)n * 128 + (c - 128));
        float4 v = *reinterpret_cast<const float4*>(W);
        uint2 o;
        o.x = h2_to_u32(__floats2half2_rn(v.x, v.y));
        o.y = h2_to_u32(__floats2half2_rn(v.z, v.w));
        wh[k] = o;
    }
}

__device__ __forceinline__ bool load_edge(const void* ei_raw, int E, int N,
                                          int e, int& s, int& d) {
    long long sl, dl;
    if (g_is64) {
        const long long* ei = (const long long*)ei_raw;
        sl = ei[e]; dl = ei[(size_t)E + e];
    } else {
        const int* ei = (const int*)ei_raw;
        sl = ei[e]; dl = ei[(size_t)E + e];
    }
    if ((unsigned long long)sl >= (unsigned long long)N ||
        (unsigned long long)dl >= (unsigned long long)N) return false;
    s = (int)sl; d = (int)dl;
    return true;
}

// ---------------------------------------------------------------------------
// Kernel B: count degrees; atomic return value = unique slot per endpoint
// ---------------------------------------------------------------------------
__global__ void count_kernel(const void* __restrict__ ei_raw, int E, int N) {
    int e = blockIdx.x * blockDim.x + threadIdx.x;
    if (e >= E) return;
    int s, d;
    if (!load_edge(ei_raw, E, N, e, s, d)) { g_slotS[e] = -1; return; }
    g_slotS[e] = atomicAdd(&g_degI[s], 1);
    g_slotD[e] = atomicAdd(&g_degI[d], 1);
}

// ---------------------------------------------------------------------------
// Kernel C: allocate segments — warp-aggregated scan, 1 atomic per warp
// ---------------------------------------------------------------------------
__global__ void alloc_kernel(int N) {
    int i = blockIdx.x * blockDim.x + threadIdx.x;
    int lane = threadIdx.x & 31;
    int deg = (i < N) ? g_degI[i] : 0;
    int sum = deg;
#pragma unroll
    for (int off = 1; off < 32; off <<= 1) {
        int v = __shfl_up_sync(0xFFFFFFFF, sum, off);
        if (lane >= off) sum += v;
    }
    int total = __shfl_sync(0xFFFFFFFF, sum, 31);
    int base = 0;
    if (lane == 31) base = atomicAdd(&g_cursor, total);
    base = __shfl_sync(0xFFFFFFFF, base, 31);
    if (i < N) g_rowStart[i] = base + sum - deg;
}

// ---------------------------------------------------------------------------
// Kernel D: fill adjacency — no atomics (slots precomputed by count)
// ---------------------------------------------------------------------------
__global__ void fill_kernel(const void* __restrict__ ei_raw, int E, int N) {
    int e = blockIdx.x * blockDim.x + threadIdx.x;
    if (e >= E) return;
    int ps = g_slotS[e];
    if (ps < 0) return;
    int s, d;
    (void)load_edge(ei_raw, E, N, e, s, d);
    int pd = g_slotD[e];
    g_nbr[g_rowStart[s] + ps] = d;
    g_nbr[g_rowStart[d] + pd] = s;
}

// ---------------------------------------------------------------------------
// Kernel E: gather on fp16 features. One warp per node; lane holds 4 halfs.
// agg_h[i] = fp16( sum(x_h[nbr]) / max(deg,1) ), accumulated in fp32.
// ---------------------------------------------------------------------------
__global__ void gather_kernel(int N) {
    int warp = (blockIdx.x * blockDim.x + threadIdx.x) >> 5;
    int lane = threadIdx.x & 31;
    if (warp >= N) return;

    int start = g_rowStart[warp];
    int deg   = g_degI[warp];
    int end   = start + deg;

    const uint2* xh = reinterpret_cast<const uint2*>(g_xh);  // 32 uint2 per row
    float4 acc = make_float4(0.f, 0.f, 0.f, 0.f);

    int j = start;
    for (; j + 8 <= end; j += 8) {
        int n[8];
#pragma unroll
        for (int u = 0; u < 8; u++) n[u] = g_nbr[j + u];
        uint2 v[8];
#pragma unroll
        for (int u = 0; u < 8; u++) v[u] = xh[(size_t)n[u] * 32 + lane];
#pragma unroll
        for (int u = 0; u < 8; u++) {
            float2 f0 = __half22float2(u32_to_h2(v[u].x));
            float2 f1 = __half22float2(u32_to_h2(v[u].y));
            acc.x += f0.x; acc.y += f0.y; acc.z += f1.x; acc.w += f1.y;
        }
    }
    for (; j < end; j++) {
        uint2 v = xh[(size_t)g_nbr[j] * 32 + lane];
        float2 f0 = __half22float2(u32_to_h2(v.x));
        float2 f1 = __half22float2(u32_to_h2(v.y));
        acc.x += f0.x; acc.y += f0.y; acc.z += f1.x; acc.w += f1.y;
    }

    float inv = 1.0f / fmaxf((float)deg, 1.0f);
    uint2 o;
    o.x = h2_to_u32(__floats2half2_rn(acc.x * inv, acc.y * inv));
    o.y = h2_to_u32(__floats2half2_rn(acc.z * inv, acc.w * inv));
    reinterpret_cast<uint2*>(g_ah)[(size_t)warp * 32 + lane] = o;
}

// ---------------------------------------------------------------------------
// Kernel F: fp16 mma.sync GEMM (m16n8k16, fp32 accum), register double-buffer.
// out = relu([x_h | agg_h] @ W_h^T + bias)
// CTA: 128x128, K=256 in 8 chunks of 32 halfs. 8 warps = 2(m) x 4(n).
// SMEM: uint32[128][20] per tile (half2 packed, LDH=20 -> conflict-free).
// ---------------------------------------------------------------------------
#define LDH 20

__device__ __forceinline__ void mma_f16(float* c, const uint32_t* a, const uint32_t* b) {
    asm volatile(
        "mma.sync.aligned.m16n8k16.row.col.f32.f16.f16.f32 "
        "{%0,%1,%2,%3}, {%4,%5,%6,%7}, {%8,%9}, {%0,%1,%2,%3};"
        : "+f"(c[0]), "+f"(c[1]), "+f"(c[2]), "+f"(c[3])
        : "r"(a[0]), "r"(a[1]), "r"(a[2]), "r"(a[3]), "r"(b[0]), "r"(b[1]));
}

__global__ __launch_bounds__(256) void gemm_mma_kernel(
    const float* __restrict__ bias,
    float* __restrict__ out,
    int N)
{
    __shared__ uint32_t As[128][LDH];
    __shared__ uint32_t Bs[128][LDH];

    int tid  = threadIdx.x;
    int wid  = tid >> 5;
    int lane = tid & 31;
    int g    = lane >> 2;
    int t    = lane & 3;
    int wm   = wid >> 2;
    int wn   = wid & 3;
    int r0   = blockIdx.x * 128;

    // tile = 128 rows x 32 halfs = 512 uint4 slots; 2 per thread
    int arow[2], aq[2];
#pragma unroll
    for (int i = 0; i < 2; i++) {
        int idx = tid + 256 * i;
        arow[i] = idx >> 2;
        aq[i]   = idx & 3;
    }

    float acc[4][4][4];
#pragma unroll
    for (int mf = 0; mf < 4; mf++)
#pragma unroll
        for (int nf = 0; nf < 4; nf++)
#pragma unroll
            for (int i = 0; i < 4; i++) acc[mf][nf][i] = 0.f;

    uint4 ra[2], rb[2];
    const uint4 zero4 = make_uint4(0u, 0u, 0u, 0u);

    // prologue: chunk 0 (k halfs [0,32) -> x_h region)
#pragma unroll
    for (int i = 0; i < 2; i++) {
        int node = r0 + arow[i];
        int koff = aq[i] * 8;
        ra[i] = (node < N)
            ? *reinterpret_cast<const uint4*>(g_xh + (size_t)node * DIM + koff)
            : zero4;
        rb[i] = *reinterpret_cast<const uint4*>(g_wh + (size_t)arow[i] * 256 + koff);
    }

    for (int c = 0; c < 8; c++) {
        // ---- store current chunk regs -> smem ----
#pragma unroll
        for (int i = 0; i < 2; i++) {
            *reinterpret_cast<uint4*>(&As[arow[i]][aq[i] * 4]) = ra[i];
            *reinterpret_cast<uint4*>(&Bs[arow[i]][aq[i] * 4]) = rb[i];
        }
        __syncthreads();

        // ---- prefetch next chunk (overlaps MMA) ----
        if (c < 7) {
            int cn = c + 1;
#pragma unroll
            for (int i = 0; i < 2; i++) {
                int node = r0 + arow[i];
                int kh = cn * 32 + aq[i] * 8;          // half index 0..255
                if (node < N) {
                    const __half* src = (kh < DIM)
                        ? (g_xh + (size_t)node * DIM + kh)
                        : (g_ah + (size_t)node * DIM + (kh - DIM));
                    ra[i] = *reinterpret_cast<const uint4*>(src);
                } else {
                    ra[i] = zero4;
                }
                rb[i] = *reinterpret_cast<const uint4*>(g_wh + (size_t)arow[i] * 256 + kh);
            }
        }

        // ---- MMA: 2 K-steps of 16 halfs ----
#pragma unroll
        for (int s = 0; s < 2; s++) {
            int k0 = s * 8;    // uint32 column
            uint32_t a[4][4];
#pragma unroll
            for (int mf = 0; mf < 4; mf++) {
                int m0 = wm * 64 + mf * 16;
                a[mf][0] = As[m0 + g][k0 + t];
                a[mf][1] = As[m0 + g + 8][k0 + t];
                a[mf][2] = As[m0 + g][k0 + t + 4];
                a[mf][3] = As[m0 + g + 8][k0 + t + 4];
            }
            uint32_t b[4][2];
#pragma unroll
            for (int nf = 0; nf < 4; nf++) {
                int n0 = wn * 32 + nf * 8;
                b[nf][0] = Bs[n0 + g][k0 + t];
                b[nf][1] = Bs[n0 + g][k0 + t + 4];
            }
#pragma unroll
            for (int mf = 0; mf < 4; mf++)
#pragma unroll
                for (int nf = 0; nf < 4; nf++)
                    mma_f16(acc[mf][nf], a[mf], b[nf]);
        }
        __syncthreads();
    }

    // ---- epilogue: bias + relu (fp32 out) ----
#pragma unroll
    for (int mf = 0; mf < 4; mf++) {
        int rA = r0 + wm * 64 + mf * 16 + g;
        int rB = rA + 8;
#pragma unroll
        for (int nf = 0; nf < 4; nf++) {
            int col = wn * 32 + nf * 8 + 2 * t;
            float2 bv = *reinterpret_cast<const float2*>(bias + col);
            if (rA < N) {
                float2 o;
                o.x = fmaxf(acc[mf][nf][0] + bv.x, 0.f);
                o.y = fmaxf(acc[mf][nf][1] + bv.y, 0.f);
                *reinterpret_cast<float2*>(out + (size_t)rA * DIM + col) = o;
            }
            if (rB < N) {
                float2 o;
                o.x = fmaxf(acc[mf][nf][2] + bv.x, 0.f);
                o.y = fmaxf(acc[mf][nf][3] + bv.y, 0.f);
                *reinterpret_cast<float2*>(out + (size_t)rB * DIM + col) = o;
            }
        }
    }
}

// ---------------------------------------------------------------------------
// Launch
// ---------------------------------------------------------------------------
extern "C" void kernel_launch(void* const* d_in, const int* in_sizes, int n_in,
                              void* d_out, int out_size) {
    const float* x  = (const float*)d_in[0];
    const void*  ei = d_in[1];

    int N = in_sizes[0] / DIM;          // 100000
    int E = in_sizes[1] / 2;            // 800000

    int iW = (n_in >= 6 && in_sizes[2] == 1) ? 3 : 2;
    const float* Ws   = (const float*)d_in[iW];
    const float* Wn   = (const float*)d_in[iW + 1];
    const float* bias = (const float*)d_in[iW + 2];
    float* out = (float*)d_out;

    init_probe_kernel<<<512, 256>>>((const long long*)ei, N, (long long)N);

    convert_kernel<<<2048, 256>>>(x, Ws, Wn, N);

    int eblocks = (E + 255) / 256;
    count_kernel<<<eblocks, 256>>>(ei, E, N);

    alloc_kernel<<<(N + 255) / 256, 256>>>(N);

    fill_kernel<<<eblocks, 256>>>(ei, E, N);

    gather_kernel<<<(N + 7) / 8, 256>>>(N);

    int gblocks = (N + 127) / 128;
    gemm_mma_kernel<<<gblocks, 256>>>(bias, out, N);
}

// round 9
// speedup vs baseline: 2.8467x; 1.0045x over previous
#include <cuda_runtime.h>
#include <cuda_fp16.h>
#include <cstdint>

// ---------------------------------------------------------------------------
// GraphSAGE layer on GB300 (sm_103 baseline -> mma.sync fp16/fp32-acc)
// CSR two-phase aggregation over fp16 features + cp.async-pipelined fp16 GEMM.
//   agg[i] = mean over neighbors (bidirectional) of x
//   out = relu( x @ Ws^T + agg @ Wn^T + bias )   (fp32 out)
// N = 100000, in_dim = out_dim = 128, E = 800000 undirected (1.6M directed)
// ---------------------------------------------------------------------------

#define MAXN 100000
#define MAXE 800000
#define DIM  128

__device__ __align__(16) __half g_xh [(size_t)MAXN * DIM];   // fp16 x
__device__ __align__(16) __half g_ah [(size_t)MAXN * DIM];   // fp16 agg (normalized)
__device__ __align__(16) __half g_wh [128 * 256];            // fused [Ws|Wn]
__device__ int g_degI[MAXN];
__device__ int g_rowStart[MAXN];
__device__ int g_nbr[2 * MAXE];
__device__ int g_slotS[MAXE];
__device__ int g_slotD[MAXE];
__device__ int g_cursor;
__device__ int g_is64;

__device__ __forceinline__ uint32_t h2_to_u32(__half2 h) {
    uint32_t u;
    *reinterpret_cast<__half2*>(&u) = h;
    return u;
}
__device__ __forceinline__ __half2 u32_to_h2(uint32_t u) {
    return *reinterpret_cast<__half2*>(&u);
}
__device__ __forceinline__ uint32_t smem_u32(const void* p) {
    return (uint32_t)__cvta_generic_to_shared(p);
}
// 16B async copy; pred=false -> zero-fill destination
__device__ __forceinline__ void cp16(uint32_t dst, const void* src, bool pred) {
    int sz = pred ? 16 : 0;
    asm volatile("cp.async.cg.shared.global [%0], [%1], 16, %2;"
                 :: "r"(dst), "l"(src), "r"(sz) : "memory");
}

// ---------------------------------------------------------------------------
// Kernel A: zero degI + cursor, probe edge dtype (JAX may emit int32/int64)
// ---------------------------------------------------------------------------
__global__ void init_probe_kernel(const long long* __restrict__ ei64,
                                  int n_deg, long long N) {
    int i = blockIdx.x * blockDim.x + threadIdx.x;
    int stride = gridDim.x * blockDim.x;
    if (i == 0) {
        int is64 = 1;
#pragma unroll
        for (int k = 0; k < 4; k++)
            if ((unsigned long long)ei64[k] >= (unsigned long long)N) is64 = 0;
        g_is64 = is64;
        g_cursor = 0;
    }
    for (int k = i; k < n_deg; k += stride) g_degI[k] = 0;
}

__device__ __forceinline__ bool load_edge(const void* ei_raw, int E, int N,
                                          int e, int& s, int& d) {
    long long sl, dl;
    if (g_is64) {
        const long long* ei = (const long long*)ei_raw;
        sl = ei[e]; dl = ei[(size_t)E + e];
    } else {
        const int* ei = (const int*)ei_raw;
        sl = ei[e]; dl = ei[(size_t)E + e];
    }
    if ((unsigned long long)sl >= (unsigned long long)N ||
        (unsigned long long)dl >= (unsigned long long)N) return false;
    s = (int)sl; d = (int)dl;
    return true;
}

// ---------------------------------------------------------------------------
// Kernel B: count degrees (slots via atomic returns) FUSED with fp16 convert.
// The two workloads are independent; grid-striding both lets the atomic-bound
// edge pass and the bandwidth-bound convert pass share the machine.
// ---------------------------------------------------------------------------
__global__ void count_convert_kernel(const void* __restrict__ ei_raw,
                                     const float* __restrict__ x,
                                     const float* __restrict__ Ws,
                                     const float* __restrict__ Wn,
                                     int E, int N) {
    int gid = blockIdx.x * blockDim.x + threadIdx.x;
    int stride = gridDim.x * blockDim.x;

    // --- edge counting ---
    for (int e = gid; e < E; e += stride) {
        int s, d;
        if (!load_edge(ei_raw, E, N, e, s, d)) { g_slotS[e] = -1; continue; }
        g_slotS[e] = atomicAdd(&g_degI[s], 1);
        g_slotD[e] = atomicAdd(&g_degI[d], 1);
    }

    // --- convert x -> fp16 ---
    const float4* x4 = reinterpret_cast<const float4*>(x);
    uint2* xh = reinterpret_cast<uint2*>(g_xh);
    int total = N * (DIM / 4);
    for (int k = gid; k < total; k += stride) {
        float4 v = x4[k];
        uint2 o;
        o.x = h2_to_u32(__floats2half2_rn(v.x, v.y));
        o.y = h2_to_u32(__floats2half2_rn(v.z, v.w));
        xh[k] = o;
    }

    // --- convert fused weights -> fp16 ---
    uint2* wh = reinterpret_cast<uint2*>(g_wh);
    int wtotal = 128 * 256 / 4;
    for (int k = gid; k < wtotal; k += stride) {
        int n = (k * 4) >> 8;
        int c = (k * 4) & 255;
        const float* W = (c < 128) ? (Ws + (size_t)n * 128 + c)
                                   : (Wn + (size_t)n * 128 + (c - 128));
        float4 v = *reinterpret_cast<const float4*>(W);
        uint2 o;
        o.x = h2_to_u32(__floats2half2_rn(v.x, v.y));
        o.y = h2_to_u32(__floats2half2_rn(v.z, v.w));
        wh[k] = o;
    }
}

// ---------------------------------------------------------------------------
// Kernel C: allocate segments — warp-aggregated scan, 1 atomic per warp
// ---------------------------------------------------------------------------
__global__ void alloc_kernel(int N) {
    int i = blockIdx.x * blockDim.x + threadIdx.x;
    int lane = threadIdx.x & 31;
    int deg = (i < N) ? g_degI[i] : 0;
    int sum = deg;
#pragma unroll
    for (int off = 1; off < 32; off <<= 1) {
        int v = __shfl_up_sync(0xFFFFFFFF, sum, off);
        if (lane >= off) sum += v;
    }
    int total = __shfl_sync(0xFFFFFFFF, sum, 31);
    int base = 0;
    if (lane == 31) base = atomicAdd(&g_cursor, total);
    base = __shfl_sync(0xFFFFFFFF, base, 31);
    if (i < N) g_rowStart[i] = base + sum - deg;
}

// ---------------------------------------------------------------------------
// Kernel D: fill adjacency — no atomics (slots precomputed)
// ---------------------------------------------------------------------------
__global__ void fill_kernel(const void* __restrict__ ei_raw, int E, int N) {
    int e = blockIdx.x * blockDim.x + threadIdx.x;
    if (e >= E) return;
    int ps = g_slotS[e];
    if (ps < 0) return;
    int s, d;
    (void)load_edge(ei_raw, E, N, e, s, d);
    int pd = g_slotD[e];
    g_nbr[g_rowStart[s] + ps] = d;
    g_nbr[g_rowStart[d] + pd] = s;
}

// ---------------------------------------------------------------------------
// Kernel E: gather on fp16 features. One warp per node; lane holds 4 halfs.
// ---------------------------------------------------------------------------
__global__ void gather_kernel(int N) {
    int warp = (blockIdx.x * blockDim.x + threadIdx.x) >> 5;
    int lane = threadIdx.x & 31;
    if (warp >= N) return;

    int start = g_rowStart[warp];
    int deg   = g_degI[warp];
    int end   = start + deg;

    const uint2* xh = reinterpret_cast<const uint2*>(g_xh);
    float4 acc = make_float4(0.f, 0.f, 0.f, 0.f);

    int j = start;
    for (; j + 8 <= end; j += 8) {
        int n[8];
#pragma unroll
        for (int u = 0; u < 8; u++) n[u] = g_nbr[j + u];
        uint2 v[8];
#pragma unroll
        for (int u = 0; u < 8; u++) v[u] = xh[(size_t)n[u] * 32 + lane];
#pragma unroll
        for (int u = 0; u < 8; u++) {
            float2 f0 = __half22float2(u32_to_h2(v[u].x));
            float2 f1 = __half22float2(u32_to_h2(v[u].y));
            acc.x += f0.x; acc.y += f0.y; acc.z += f1.x; acc.w += f1.y;
        }
    }
    for (; j < end; j++) {
        uint2 v = xh[(size_t)g_nbr[j] * 32 + lane];
        float2 f0 = __half22float2(u32_to_h2(v.x));
        float2 f1 = __half22float2(u32_to_h2(v.y));
        acc.x += f0.x; acc.y += f0.y; acc.z += f1.x; acc.w += f1.y;
    }

    float inv = 1.0f / fmaxf((float)deg, 1.0f);
    uint2 o;
    o.x = h2_to_u32(__floats2half2_rn(acc.x * inv, acc.y * inv));
    o.y = h2_to_u32(__floats2half2_rn(acc.z * inv, acc.w * inv));
    reinterpret_cast<uint2*>(g_ah)[(size_t)warp * 32 + lane] = o;
}

// ---------------------------------------------------------------------------
// Kernel F: fp16 mma.sync GEMM, cp.async double-buffered SMEM pipeline.
// out = relu([x_h | agg_h] @ W_h^T + bias)
// CTA: 128x128, K=256 in 8 chunks of 32 halfs. 8 warps = 2(m) x 4(n).
// ---------------------------------------------------------------------------
#define LDH 20

__device__ __forceinline__ void mma_f16(float* c, const uint32_t* a, const uint32_t* b) {
    asm volatile(
        "mma.sync.aligned.m16n8k16.row.col.f32.f16.f16.f32 "
        "{%0,%1,%2,%3}, {%4,%5,%6,%7}, {%8,%9}, {%0,%1,%2,%3};"
        : "+f"(c[0]), "+f"(c[1]), "+f"(c[2]), "+f"(c[3])
        : "r"(a[0]), "r"(a[1]), "r"(a[2]), "r"(a[3]), "r"(b[0]), "r"(b[1]));
}

__global__ __launch_bounds__(256) void gemm_mma_kernel(
    const float* __restrict__ bias,
    float* __restrict__ out,
    int N)
{
    __shared__ uint32_t As[2][128][LDH];
    __shared__ uint32_t Bs[2][128][LDH];

    int tid  = threadIdx.x;
    int wid  = tid >> 5;
    int lane = tid & 31;
    int g    = lane >> 2;
    int t    = lane & 3;
    int wm   = wid >> 2;
    int wn   = wid & 3;
    int r0   = blockIdx.x * 128;

    // tile = 128 rows x 32 halfs = 512 uint4 slots; 2 per thread
    int arow[2], aq[2];
#pragma unroll
    for (int i = 0; i < 2; i++) {
        int idx = tid + 256 * i;
        arow[i] = idx >> 2;
        aq[i]   = idx & 3;
    }

    float acc[4][4][4];
#pragma unroll
    for (int mf = 0; mf < 4; mf++)
#pragma unroll
        for (int nf = 0; nf < 4; nf++)
#pragma unroll
            for (int i = 0; i < 4; i++) acc[mf][nf][i] = 0.f;

    // async-issue one chunk into buffer buf
    auto issue = [&](int c, int buf) {
#pragma unroll
        for (int i = 0; i < 2; i++) {
            int node = r0 + arow[i];
            int kh = c * 32 + aq[i] * 8;           // half index 0..255
            const __half* srcA = (kh < DIM)
                ? (g_xh + (size_t)node * DIM + kh)
                : (g_ah + (size_t)node * DIM + (kh - DIM));
            cp16(smem_u32(&As[buf][arow[i]][aq[i] * 4]), srcA, node < N);
            cp16(smem_u32(&Bs[buf][arow[i]][aq[i] * 4]),
                 g_wh + (size_t)arow[i] * 256 + kh, true);
        }
    };

    issue(0, 0);
    asm volatile("cp.async.commit_group;" ::: "memory");

    for (int c = 0; c < 8; c++) {
        int buf = c & 1;
        if (c < 7) {
            issue(c + 1, buf ^ 1);
            asm volatile("cp.async.commit_group;" ::: "memory");
            asm volatile("cp.async.wait_group 1;" ::: "memory");
        } else {
            asm volatile("cp.async.wait_group 0;" ::: "memory");
        }
        __syncthreads();

        // ---- MMA: 2 K-steps of 16 halfs ----
#pragma unroll
        for (int s = 0; s < 2; s++) {
            int k0 = s * 8;
            uint32_t a[4][4];
#pragma unroll
            for (int mf = 0; mf < 4; mf++) {
                int m0 = wm * 64 + mf * 16;
                a[mf][0] = As[buf][m0 + g][k0 + t];
                a[mf][1] = As[buf][m0 + g + 8][k0 + t];
                a[mf][2] = As[buf][m0 + g][k0 + t + 4];
                a[mf][3] = As[buf][m0 + g + 8][k0 + t + 4];
            }
            uint32_t b[4][2];
#pragma unroll
            for (int nf = 0; nf < 4; nf++) {
                int n0 = wn * 32 + nf * 8;
                b[nf][0] = Bs[buf][n0 + g][k0 + t];
                b[nf][1] = Bs[buf][n0 + g][k0 + t + 4];
            }
#pragma unroll
            for (int mf = 0; mf < 4; mf++)
#pragma unroll
                for (int nf = 0; nf < 4; nf++)
                    mma_f16(acc[mf][nf], a[mf], b[nf]);
        }
        __syncthreads();   // buffer reuse barrier (issue c+2 targets buf)
    }

    // ---- epilogue: bias + relu (fp32 out) ----
#pragma unroll
    for (int mf = 0; mf < 4; mf++) {
        int rA = r0 + wm * 64 + mf * 16 + g;
        int rB = rA + 8;
#pragma unroll
        for (int nf = 0; nf < 4; nf++) {
            int col = wn * 32 + nf * 8 + 2 * t;
            float2 bv = *reinterpret_cast<const float2*>(bias + col);
            if (rA < N) {
                float2 o;
                o.x = fmaxf(acc[mf][nf][0] + bv.x, 0.f);
                o.y = fmaxf(acc[mf][nf][1] + bv.y, 0.f);
                *reinterpret_cast<float2*>(out + (size_t)rA * DIM + col) = o;
            }
            if (rB < N) {
                float2 o;
                o.x = fmaxf(acc[mf][nf][2] + bv.x, 0.f);
                o.y = fmaxf(acc[mf][nf][3] + bv.y, 0.f);
                *reinterpret_cast<float2*>(out + (size_t)rB * DIM + col) = o;
            }
        }
    }
}

// ---------------------------------------------------------------------------
// Launch
// ---------------------------------------------------------------------------
extern "C" void kernel_launch(void* const* d_in, const int* in_sizes, int n_in,
                              void* d_out, int out_size) {
    const float* x  = (const float*)d_in[0];
    const void*  ei = d_in[1];

    int N = in_sizes[0] / DIM;          // 100000
    int E = in_sizes[1] / 2;            // 800000

    int iW = (n_in >= 6 && in_sizes[2] == 1) ? 3 : 2;
    const float* Ws   = (const float*)d_in[iW];
    const float* Wn   = (const float*)d_in[iW + 1];
    const float* bias = (const float*)d_in[iW + 2];
    float* out = (float*)d_out;

    init_probe_kernel<<<512, 256>>>((const long long*)ei, N, (long long)N);

    count_convert_kernel<<<4096, 256>>>(ei, x, Ws, Wn, E, N);

    alloc_kernel<<<(N + 255) / 256, 256>>>(N);

    int eblocks = (E + 255) / 256;
    fill_kernel<<<eblocks, 256>>>(ei, E, N);

    gather_kernel<<<(N + 7) / 8, 256>>>(N);

    int gblocks = (N + 127) / 128;
    gemm_mma_kernel<<<gblocks, 256>>>(bias, out, N);
}